// round 3
// baseline (speedup 1.0000x reference)
#include <cuda_runtime.h>
#include <cstddef>

typedef unsigned long long u64;

// M matrix, TRANSPOSED splat layout:
//   g_M[((g*32 + k)*16 + j)*2 + {0,1}] = U_g[j][k]   (value duplicated)
// One (g,k) column = 16 splat pairs = 128B; row-half h occupies 64B of it.
__device__ float g_M[4 * 32 * 16 * 2];

// ---------------------------------------------------------------------------
// Precompute: simulate the weight-only circuit on all 32 basis states for
// each of the 4 generators. Thread t = g*32 + k simulates column k of U_g.
// ---------------------------------------------------------------------------
__global__ void precompute_M_kernel(const float* __restrict__ qp)
{
    int t = threadIdx.x;
    if (t >= 128) return;
    int g = t >> 5;
    int k = t & 31;

    float st[32];
#pragma unroll
    for (int i = 0; i < 32; ++i) st[i] = 0.0f;
    st[k] = 1.0f;

#pragma unroll 1
    for (int d = 0; d < 6; ++d) {
#pragma unroll
        for (int w = 0; w < 5; ++w) {
            float th = qp[g * 30 + d * 5 + w] * 0.5f;
            float s, c;
            sincosf(th, &s, &c);
            const int stride = 16 >> w;
#pragma unroll
            for (int i = 0; i < 32; ++i) {
                if (i & stride) continue;
                float a0 = st[i];
                float a1 = st[i + stride];
                st[i]          = c * a0 - s * a1;
                st[i + stride] = s * a0 + c * a1;
            }
        }
#pragma unroll
        for (int w = 0; w < 4; ++w) {
            const int m = (16 >> w) | (8 >> w);
#pragma unroll
            for (int i = 0; i < 32; ++i)
                if ((i & m) == m) st[i] = -st[i];
        }
    }

#pragma unroll
    for (int j = 0; j < 16; ++j) {
        g_M[((g * 32 + k) * 16 + j) * 2 + 0] = st[j];
        g_M[((g * 32 + k) * 16 + j) * 2 + 1] = st[j];
    }
}

// ---------------------------------------------------------------------------
// Packed f32x2 helpers (Blackwell sm_103a)
// ---------------------------------------------------------------------------
__device__ __forceinline__ u64 pk2(float lo, float hi) {
    u64 r;
    asm("mov.b64 %0, {%1, %2};" : "=l"(r) : "f"(lo), "f"(hi));
    return r;
}
__device__ __forceinline__ void upk2(u64 v, float& lo, float& hi) {
    asm("mov.b64 {%0, %1}, %2;" : "=f"(lo), "=f"(hi) : "l"(v));
}
__device__ __forceinline__ u64 fma2(u64 a, u64 b, u64 c) {
    u64 d;
    asm("fma.rn.f32x2 %0, %1, %2, %3;" : "=l"(d) : "l"(a), "l"(b), "l"(c));
    return d;
}
__device__ __forceinline__ u64 mul2(u64 a, u64 b) {
    u64 d;
    asm("mul.rn.f32x2 %0, %1, %2;" : "=l"(d) : "l"(a), "l"(b));
    return d;
}

// Build Kronecker factors for one f32x2 pair of batch elements.
__device__ __forceinline__ void build_psi_factors(
    float4 qa, float4 qb, u64 pa[8], u64 pb[4])
{
    float c[5][2], s[5][2];
#pragma unroll
    for (int e = 0; e < 2; ++e) {
        float a0 = e ? qb.x : qa.x;
        float a1 = e ? qb.y : qa.y;
        float a2 = e ? qb.z : qa.z;
        float h0 = 0.5f   * a0;
        float h1 = 0.375f * a0 + 0.125f * a1;
        float h2 = 0.125f * a0 + 0.375f * a1;
        float h3 = 0.375f * a1 + 0.125f * a2;
        float h4 = 0.125f * a1 + 0.375f * a2;
        __sincosf(h0, &s[0][e], &c[0][e]);
        __sincosf(h1, &s[1][e], &c[1][e]);
        __sincosf(h2, &s[2][e], &c[2][e]);
        __sincosf(h3, &s[3][e], &c[3][e]);
        __sincosf(h4, &s[4][e], &c[4][e]);
    }
    u64 cp[5], sp[5];
#pragma unroll
    for (int w = 0; w < 5; ++w) {
        cp[w] = pk2(c[w][0], c[w][1]);
        sp[w] = pk2(s[w][0], s[w][1]);
    }
    u64 t01[4];
    t01[0] = mul2(cp[0], cp[1]);
    t01[1] = mul2(cp[0], sp[1]);
    t01[2] = mul2(sp[0], cp[1]);
    t01[3] = mul2(sp[0], sp[1]);
#pragma unroll
    for (int i = 0; i < 4; ++i) {
        pa[2 * i + 0] = mul2(t01[i], cp[2]);
        pa[2 * i + 1] = mul2(t01[i], sp[2]);
    }
    pb[0] = mul2(cp[3], cp[4]);
    pb[1] = mul2(cp[3], sp[4]);
    pb[2] = mul2(sp[3], cp[4]);
    pb[3] = mul2(sp[3], sp[4]);
}

// ---------------------------------------------------------------------------
// Main kernel: 4 batch elements per thread (2 f32x2 pairs); output rows
// processed in two halves of 8 to keep live accumulators at 16 u64.
// ---------------------------------------------------------------------------
__global__ void __launch_bounds__(256, 2) qsrgan_main_kernel(
    const float* __restrict__ in,
    float* __restrict__ out,
    int B)
{
    __shared__ __align__(16) float sM[4 * 32 * 16 * 2];  // 16 KB
    {
        const float4* src = (const float4*)g_M;
        float4* dst = (float4*)sM;
#pragma unroll
        for (int i = threadIdx.x; i < 1024; i += 256)
            dst[i] = src[i];
    }
    __syncthreads();

    long long b = ((long long)blockIdx.x * 256 + threadIdx.x) * 4;
    if (b >= B) return;
    long long i1 = (b + 1 < B) ? b + 1 : b;
    long long i2 = (b + 2 < B) ? b + 2 : b;
    long long i3 = (b + 3 < B) ? b + 3 : b;

    float4 q0 = *(const float4*)(in + b  * 16);
    float4 q1 = *(const float4*)(in + i1 * 16);
    float4 q2 = *(const float4*)(in + i2 * 16);
    float4 q3 = *(const float4*)(in + i3 * 16);

    u64 pa0[8], pb0[4], pa1[8], pb1[4];
    build_psi_factors(q0, q1, pa0, pb0);
    build_psi_factors(q2, q3, pa1, pb1);

#pragma unroll 1
    for (int g = 0; g < 4; ++g) {
        float sq[16][4];      // squares for all 16 rows x 4 elements
        float mx0 = 0.0f, mx1 = 0.0f, mx2 = 0.0f, mx3 = 0.0f;

#pragma unroll
        for (int half = 0; half < 2; ++half) {
            u64 acc[8][2];
#pragma unroll
            for (int j = 0; j < 8; ++j) { acc[j][0] = 0ULL; acc[j][1] = 0ULL; }

#pragma unroll
            for (int ka = 0; ka < 8; ++ka) {
#pragma unroll
                for (int kb = 0; kb < 4; ++kb) {
                    const int k = ka * 4 + kb;
                    u64 pk0 = mul2(pa0[ka], pb0[kb]);
                    u64 pk1 = mul2(pa1[ka], pb1[kb]);
                    const ulonglong2* col =
                        (const ulonglong2*)sM + (g * 32 + k) * 8 + half * 4;
#pragma unroll
                    for (int j2 = 0; j2 < 4; ++j2) {
                        ulonglong2 mv = col[j2];
                        acc[2 * j2 + 0][0] = fma2(mv.x, pk0, acc[2 * j2 + 0][0]);
                        acc[2 * j2 + 0][1] = fma2(mv.x, pk1, acc[2 * j2 + 0][1]);
                        acc[2 * j2 + 1][0] = fma2(mv.y, pk0, acc[2 * j2 + 1][0]);
                        acc[2 * j2 + 1][1] = fma2(mv.y, pk1, acc[2 * j2 + 1][1]);
                    }
                }
            }

#pragma unroll
            for (int j = 0; j < 8; ++j) {
                float yA, yB, yC, yD;
                upk2(acc[j][0], yA, yB);
                upk2(acc[j][1], yC, yD);
                int r = half * 8 + j;
                sq[r][0] = yA * yA; mx0 = fmaxf(mx0, sq[r][0]);
                sq[r][1] = yB * yB; mx1 = fmaxf(mx1, sq[r][1]);
                sq[r][2] = yC * yC; mx2 = fmaxf(mx2, sq[r][2]);
                sq[r][3] = yD * yD; mx3 = fmaxf(mx3, sq[r][3]);
            }
        }

        float r0 = __fdividef(1.0f, mx0);
        float r1 = __fdividef(1.0f, mx1);
        float r2 = __fdividef(1.0f, mx2);
        float r3 = __fdividef(1.0f, mx3);

        {
            float4* o = (float4*)(out + b * 64 + g * 16);
#pragma unroll
            for (int q = 0; q < 4; ++q)
                o[q] = make_float4(sq[4*q+0][0]*r0, sq[4*q+1][0]*r0,
                                   sq[4*q+2][0]*r0, sq[4*q+3][0]*r0);
        }
        if (b + 1 < B) {
            float4* o = (float4*)(out + i1 * 64 + g * 16);
#pragma unroll
            for (int q = 0; q < 4; ++q)
                o[q] = make_float4(sq[4*q+0][1]*r1, sq[4*q+1][1]*r1,
                                   sq[4*q+2][1]*r1, sq[4*q+3][1]*r1);
        }
        if (b + 2 < B) {
            float4* o = (float4*)(out + i2 * 64 + g * 16);
#pragma unroll
            for (int q = 0; q < 4; ++q)
                o[q] = make_float4(sq[4*q+0][2]*r2, sq[4*q+1][2]*r2,
                                   sq[4*q+2][2]*r2, sq[4*q+3][2]*r2);
        }
        if (b + 3 < B) {
            float4* o = (float4*)(out + i3 * 64 + g * 16);
#pragma unroll
            for (int q = 0; q < 4; ++q)
                o[q] = make_float4(sq[4*q+0][3]*r3, sq[4*q+1][3]*r3,
                                   sq[4*q+2][3]*r3, sq[4*q+3][3]*r3);
        }
    }
}

// ---------------------------------------------------------------------------
extern "C" void kernel_launch(void* const* d_in, const int* in_sizes, int n_in,
                              void* d_out, int out_size)
{
    const float* in = (const float*)d_in[0];   // (B,1,4,4) f32
    const float* qp = (const float*)d_in[1];   // (4, 30) f32
    float* out = (float*)d_out;                // (B, 64) f32

    int B = in_sizes[0] / 16;
    int nthreads = (B + 3) / 4;
    int blocks = (nthreads + 255) / 256;

    precompute_M_kernel<<<1, 128>>>(qp);
    qsrgan_main_kernel<<<blocks, 256>>>(in, out, B);
}

// round 4
// speedup vs baseline: 1.2468x; 1.2468x over previous
#include <cuda_runtime.h>
#include <cstddef>

typedef unsigned long long u64;

// M matrix, TRANSPOSED splat layout:
//   g_M[((g*32 + k)*16 + j)*2 + {0,1}] = U_g[j][k]   (value duplicated)
__device__ float g_M[4 * 32 * 16 * 2];

// ---------------------------------------------------------------------------
// Precompute: simulate the weight-only circuit on all 32 basis states for
// each of the 4 generators. Thread t = g*32 + k simulates column k of U_g.
// ---------------------------------------------------------------------------
__global__ void precompute_M_kernel(const float* __restrict__ qp)
{
    int t = threadIdx.x;
    if (t >= 128) return;
    int g = t >> 5;
    int k = t & 31;

    float st[32];
#pragma unroll
    for (int i = 0; i < 32; ++i) st[i] = 0.0f;
    st[k] = 1.0f;

#pragma unroll 1
    for (int d = 0; d < 6; ++d) {
#pragma unroll
        for (int w = 0; w < 5; ++w) {
            float th = qp[g * 30 + d * 5 + w] * 0.5f;
            float s, c;
            sincosf(th, &s, &c);
            const int stride = 16 >> w;
#pragma unroll
            for (int i = 0; i < 32; ++i) {
                if (i & stride) continue;
                float a0 = st[i];
                float a1 = st[i + stride];
                st[i]          = c * a0 - s * a1;
                st[i + stride] = s * a0 + c * a1;
            }
        }
#pragma unroll
        for (int w = 0; w < 4; ++w) {
            const int m = (16 >> w) | (8 >> w);
#pragma unroll
            for (int i = 0; i < 32; ++i)
                if ((i & m) == m) st[i] = -st[i];
        }
    }

#pragma unroll
    for (int j = 0; j < 16; ++j) {
        g_M[((g * 32 + k) * 16 + j) * 2 + 0] = st[j];
        g_M[((g * 32 + k) * 16 + j) * 2 + 1] = st[j];
    }
}

// ---------------------------------------------------------------------------
// Packed f32x2 helpers (Blackwell sm_103a)
// ---------------------------------------------------------------------------
__device__ __forceinline__ u64 pk2(float lo, float hi) {
    u64 r;
    asm("mov.b64 %0, {%1, %2};" : "=l"(r) : "f"(lo), "f"(hi));
    return r;
}
__device__ __forceinline__ void upk2(u64 v, float& lo, float& hi) {
    asm("mov.b64 {%0, %1}, %2;" : "=f"(lo), "=f"(hi) : "l"(v));
}
__device__ __forceinline__ u64 fma2(u64 a, u64 b, u64 c) {
    u64 d;
    asm("fma.rn.f32x2 %0, %1, %2, %3;" : "=l"(d) : "l"(a), "l"(b), "l"(c));
    return d;
}
__device__ __forceinline__ u64 mul2(u64 a, u64 b) {
    u64 d;
    asm("mul.rn.f32x2 %0, %1, %2;" : "=l"(d) : "l"(a), "l"(b));
    return d;
}

// Build Kronecker factors for one f32x2 pair of batch elements.
__device__ __forceinline__ void build_psi_factors(
    float4 qa, float4 qb, u64 pa[8], u64 pb[4])
{
    float c[5][2], s[5][2];
#pragma unroll
    for (int e = 0; e < 2; ++e) {
        float a0 = e ? qb.x : qa.x;
        float a1 = e ? qb.y : qa.y;
        float a2 = e ? qb.z : qa.z;
        float h0 = 0.5f   * a0;
        float h1 = 0.375f * a0 + 0.125f * a1;
        float h2 = 0.125f * a0 + 0.375f * a1;
        float h3 = 0.375f * a1 + 0.125f * a2;
        float h4 = 0.125f * a1 + 0.375f * a2;
        __sincosf(h0, &s[0][e], &c[0][e]);
        __sincosf(h1, &s[1][e], &c[1][e]);
        __sincosf(h2, &s[2][e], &c[2][e]);
        __sincosf(h3, &s[3][e], &c[3][e]);
        __sincosf(h4, &s[4][e], &c[4][e]);
    }
    u64 cp[5], sp[5];
#pragma unroll
    for (int w = 0; w < 5; ++w) {
        cp[w] = pk2(c[w][0], c[w][1]);
        sp[w] = pk2(s[w][0], s[w][1]);
    }
    u64 t01[4];
    t01[0] = mul2(cp[0], cp[1]);
    t01[1] = mul2(cp[0], sp[1]);
    t01[2] = mul2(sp[0], cp[1]);
    t01[3] = mul2(sp[0], sp[1]);
#pragma unroll
    for (int i = 0; i < 4; ++i) {
        pa[2 * i + 0] = mul2(t01[i], cp[2]);
        pa[2 * i + 1] = mul2(t01[i], sp[2]);
    }
    pb[0] = mul2(cp[3], cp[4]);
    pb[1] = mul2(cp[3], sp[4]);
    pb[2] = mul2(sp[3], cp[4]);
    pb[3] = mul2(sp[3], sp[4]);
}

// ---------------------------------------------------------------------------
// Main kernel: 4 batch elements/thread (2 f32x2 pairs), all 16 rows live,
// two-pass epilogue (no sq[] array) to keep register pressure ~140.
// ---------------------------------------------------------------------------
__global__ void __launch_bounds__(128, 3) qsrgan_main_kernel(
    const float* __restrict__ in,
    float* __restrict__ out,
    int B)
{
    __shared__ __align__(16) float sM[4 * 32 * 16 * 2];  // 16 KB
    {
        const float4* src = (const float4*)g_M;
        float4* dst = (float4*)sM;
#pragma unroll
        for (int i = threadIdx.x; i < 1024; i += 128)
            dst[i] = src[i];
    }
    __syncthreads();

    long long b = ((long long)blockIdx.x * 128 + threadIdx.x) * 4;
    if (b >= B) return;
    long long i1 = (b + 1 < B) ? b + 1 : b;
    long long i2 = (b + 2 < B) ? b + 2 : b;
    long long i3 = (b + 3 < B) ? b + 3 : b;

    float4 q0 = __ldg((const float4*)(in + b  * 16));
    float4 q1 = __ldg((const float4*)(in + i1 * 16));
    float4 q2 = __ldg((const float4*)(in + i2 * 16));
    float4 q3 = __ldg((const float4*)(in + i3 * 16));

    u64 pa0[8], pb0[4], pa1[8], pb1[4];
    build_psi_factors(q0, q1, pa0, pb0);
    build_psi_factors(q2, q3, pa1, pb1);

#pragma unroll 1
    for (int g = 0; g < 4; ++g) {
        u64 acc[16][2];
#pragma unroll
        for (int j = 0; j < 16; ++j) { acc[j][0] = 0ULL; acc[j][1] = 0ULL; }

#pragma unroll 4
        for (int ka = 0; ka < 8; ++ka) {
#pragma unroll
            for (int kb = 0; kb < 4; ++kb) {
                const int k = ka * 4 + kb;
                u64 pk0 = mul2(pa0[ka], pb0[kb]);
                u64 pk1 = mul2(pa1[ka], pb1[kb]);
                const ulonglong2* col = (const ulonglong2*)sM + (g * 32 + k) * 8;
#pragma unroll
                for (int j2 = 0; j2 < 8; ++j2) {
                    ulonglong2 mv = col[j2];
                    acc[2 * j2 + 0][0] = fma2(mv.x, pk0, acc[2 * j2 + 0][0]);
                    acc[2 * j2 + 0][1] = fma2(mv.x, pk1, acc[2 * j2 + 0][1]);
                    acc[2 * j2 + 1][0] = fma2(mv.y, pk0, acc[2 * j2 + 1][0]);
                    acc[2 * j2 + 1][1] = fma2(mv.y, pk1, acc[2 * j2 + 1][1]);
                }
            }
        }

        // Pass 1: per-element max of squares (acc stays live; no sq[] array)
        float mx0 = 0.0f, mx1 = 0.0f, mx2 = 0.0f, mx3 = 0.0f;
#pragma unroll
        for (int j = 0; j < 16; ++j) {
            float yA, yB, yC, yD;
            upk2(acc[j][0], yA, yB);
            upk2(acc[j][1], yC, yD);
            mx0 = fmaxf(mx0, yA * yA);
            mx1 = fmaxf(mx1, yB * yB);
            mx2 = fmaxf(mx2, yC * yC);
            mx3 = fmaxf(mx3, yD * yD);
        }
        float r0 = __fdividef(1.0f, mx0);
        float r1 = __fdividef(1.0f, mx1);
        float r2 = __fdividef(1.0f, mx2);
        float r3 = __fdividef(1.0f, mx3);

        // Pass 2: recompute squares from acc, scale, store (float4 per 4 rows)
        float* o0 = out + b  * 64 + g * 16;
        float* o1 = out + i1 * 64 + g * 16;
        float* o2 = out + i2 * 64 + g * 16;
        float* o3 = out + i3 * 64 + g * 16;
#pragma unroll
        for (int q = 0; q < 4; ++q) {
            float a0[4], a1[4], a2[4], a3[4];
#pragma unroll
            for (int t = 0; t < 4; ++t) {
                float yA, yB, yC, yD;
                upk2(acc[4 * q + t][0], yA, yB);
                upk2(acc[4 * q + t][1], yC, yD);
                a0[t] = yA * yA * r0;
                a1[t] = yB * yB * r1;
                a2[t] = yC * yC * r2;
                a3[t] = yD * yD * r3;
            }
            ((float4*)o0)[q] = make_float4(a0[0], a0[1], a0[2], a0[3]);
            if (b + 1 < B) ((float4*)o1)[q] = make_float4(a1[0], a1[1], a1[2], a1[3]);
            if (b + 2 < B) ((float4*)o2)[q] = make_float4(a2[0], a2[1], a2[2], a2[3]);
            if (b + 3 < B) ((float4*)o3)[q] = make_float4(a3[0], a3[1], a3[2], a3[3]);
        }
    }
}

// ---------------------------------------------------------------------------
extern "C" void kernel_launch(void* const* d_in, const int* in_sizes, int n_in,
                              void* d_out, int out_size)
{
    const float* in = (const float*)d_in[0];   // (B,1,4,4) f32
    const float* qp = (const float*)d_in[1];   // (4, 30) f32
    float* out = (float*)d_out;                // (B, 64) f32

    int B = in_sizes[0] / 16;
    int nthreads = (B + 3) / 4;
    int blocks = (nthreads + 127) / 128;

    precompute_M_kernel<<<1, 128>>>(qp);
    qsrgan_main_kernel<<<blocks, 128>>>(in, out, B);
}